// round 2
// baseline (speedup 1.0000x reference)
#include <cuda_runtime.h>

// CapsuleLayer dynamic routing, fully fused recompute (no hat materialization).
//   B=64 batch, N=4096 input caps, I=8 in-dim, C=32 out caps, D=16 out dim, 3 routings.
// Pass kernel (per routing iter): each CTA = (32 b's) x (32 n's). W staged in
// SMEM (xor-swizzled), hat recomputed in registers, softmax via 8-lane shfl,
// per-thread register accumulators for s[b,c,j], flushed to partial buffer.
// Reduce kernel: sum partials over 128 chunks, squash, update cumulative out.

#define B_ 64
#define N_ 4096
#define I_ 8
#define C_ 32
#define D_ 16
#define NB 32        // b per CTA
#define NCHUNK 32    // n per CTA
#define SUBN 4       // n per W smem stage (4 * 16KB = 64KB)
#define NCTA 128     // N_/NCHUNK
#define THREADS 256
#define OPAD 20      // padded D for O in smem (bank-friendly)

__device__ float g_part[(size_t)NCTA * B_ * C_ * D_];  // 16 MB partials [chunk][b][c][j]
__device__ float g_Ocum[B_ * C_ * D_];                 // cumulative sum of outs (for logits)

template<int ITER>
__global__ void __launch_bounds__(THREADS, 1)
caps_pass(const float* __restrict__ X, const float* __restrict__ W) {
    extern __shared__ float sm[];
    float* sW = sm;                               // SUBN*C_*D_*I_ = 16384 floats (64KB)
    float* sX = sm + SUBN * C_ * D_ * I_;         // NCHUNK*NB*I_  =  8192 floats (32KB)
    float* sO = sX + NCHUNK * NB * I_;            // NB*C_*OPAD    = 20480 floats (80KB, ITER>0)

    const int chunk = blockIdx.x;
    const int half  = blockIdx.y;
    const int n0 = chunk * NCHUNK;
    const int b0 = half * NB;
    const int tid = threadIdx.x;
    const int bl = tid >> 3;      // local b (0..31)
    const int cs = tid & 7;       // c slot; handles c = cs + 8k, k=0..3

    // ---- stage x chunk: sX[n][b][i] ----
    for (int idx = tid; idx < NCHUNK * NB * 2; idx += THREADS) {
        int bb  = idx >> 6;          // local b
        int rem = idx & 63;          // n*2 + ih
        float4 v = reinterpret_cast<const float4*>(X)
                       [(size_t)(b0 + bb) * (N_ * 2) + (size_t)n0 * 2 + rem];
        reinterpret_cast<float4*>(sX)[(rem >> 1) * (NB * 2) + bb * 2 + (rem & 1)] = v;
    }

    // ---- stage O (cumulative out) padded: sO[bl][c][OPAD] ----
    if (ITER > 0) {
        for (int row = tid; row < NB * C_; row += THREADS) {
            const float4* src = reinterpret_cast<const float4*>(g_Ocum) + (size_t)(b0 * C_ + row) * 4;
            float4* dst = reinterpret_cast<float4*>(sO + row * OPAD);
            dst[0] = src[0]; dst[1] = src[1]; dst[2] = src[2]; dst[3] = src[3];
        }
    }

    float acc[4][16];
    #pragma unroll
    for (int k = 0; k < 4; ++k)
        #pragma unroll
        for (int j = 0; j < 16; ++j) acc[k][j] = 0.f;

    for (int sub = 0; sub < NCHUNK / SUBN; ++sub) {
        __syncthreads();
        // ---- stage W sub-chunk, xor-swizzled: f4[r*32 + (c ^ (r&31))], r=(nn*16+j)*2+ih ----
        {
            const int nbase = n0 + sub * SUBN;
            for (int idx = tid; idx < C_ * SUBN * 32; idx += THREADS) {
                int c = idx >> 7;        // 0..31
                int r = idx & 127;       // 0..127
                float4 v = reinterpret_cast<const float4*>(W)
                               [(size_t)c * (N_ * 32) + (size_t)nbase * 32 + r];
                reinterpret_cast<float4*>(sW)[(r << 5) + (c ^ (r & 31))] = v;
            }
        }
        __syncthreads();

        #pragma unroll
        for (int nn = 0; nn < SUBN; ++nn) {
            const float4* xs = reinterpret_cast<const float4*>(sX) + ((sub * SUBN + nn) * NB + bl) * 2;
            const float4 x0 = xs[0], x1 = xs[1];

            float hat[4][16];
            float logit[4];
            #pragma unroll
            for (int k = 0; k < 4; ++k) {
                const int c = cs + 8 * k;
                #pragma unroll
                for (int j = 0; j < 16; ++j) {
                    const int r0 = nn * 32 + j * 2;   // r&31 == 2j (+ih), independent of nn
                    float4 w0 = reinterpret_cast<const float4*>(sW)[(r0 << 5)        + (c ^ ((2 * j)     & 31))];
                    float4 w1 = reinterpret_cast<const float4*>(sW)[((r0 + 1) << 5)  + (c ^ ((2 * j + 1) & 31))];
                    float h = x0.x * w0.x;
                    h = fmaf(x0.y, w0.y, h); h = fmaf(x0.z, w0.z, h); h = fmaf(x0.w, w0.w, h);
                    h = fmaf(x1.x, w1.x, h); h = fmaf(x1.y, w1.y, h);
                    h = fmaf(x1.z, w1.z, h); h = fmaf(x1.w, w1.w, h);
                    hat[k][j] = h;
                }
                if (ITER > 0) {
                    const float4* Ob = reinterpret_cast<const float4*>(sO + (bl * C_ + c) * OPAD);
                    float l = 0.f;
                    #pragma unroll
                    for (int jq = 0; jq < 4; ++jq) {
                        float4 o = Ob[jq];
                        l = fmaf(o.x, hat[k][4 * jq + 0], l);
                        l = fmaf(o.y, hat[k][4 * jq + 1], l);
                        l = fmaf(o.z, hat[k][4 * jq + 2], l);
                        l = fmaf(o.w, hat[k][4 * jq + 3], l);
                    }
                    logit[k] = l;
                }
            }

            if (ITER == 0) {
                // uniform coupling 1/32: accumulate raw hat, scale at flush
                #pragma unroll
                for (int k = 0; k < 4; ++k)
                    #pragma unroll
                    for (int j = 0; j < 16; ++j) acc[k][j] += hat[k][j];
            } else {
                // softmax over 32 c's: 4 local + 8-lane shfl tree (lanes of same b)
                float m = fmaxf(fmaxf(logit[0], logit[1]), fmaxf(logit[2], logit[3]));
                m = fmaxf(m, __shfl_xor_sync(0xffffffffu, m, 1));
                m = fmaxf(m, __shfl_xor_sync(0xffffffffu, m, 2));
                m = fmaxf(m, __shfl_xor_sync(0xffffffffu, m, 4));
                float e0 = __expf(logit[0] - m), e1 = __expf(logit[1] - m);
                float e2 = __expf(logit[2] - m), e3 = __expf(logit[3] - m);
                float s = (e0 + e1) + (e2 + e3);
                s += __shfl_xor_sync(0xffffffffu, s, 1);
                s += __shfl_xor_sync(0xffffffffu, s, 2);
                s += __shfl_xor_sync(0xffffffffu, s, 4);
                const float inv = __fdividef(1.f, s);
                const float cf[4] = {e0 * inv, e1 * inv, e2 * inv, e3 * inv};
                #pragma unroll
                for (int k = 0; k < 4; ++k)
                    #pragma unroll
                    for (int j = 0; j < 16; ++j)
                        acc[k][j] = fmaf(cf[k], hat[k][j], acc[k][j]);
            }
        }
    }

    // ---- flush partial sums ----
    const float scale = (ITER == 0) ? (1.f / 32.f) : 1.f;
    const int b = b0 + bl;
    #pragma unroll
    for (int k = 0; k < 4; ++k) {
        const int c = cs + 8 * k;
        float4* dst = reinterpret_cast<float4*>(g_part) + ((size_t)(chunk * B_ + b) * C_ + c) * 4;
        #pragma unroll
        for (int jq = 0; jq < 4; ++jq) {
            dst[jq] = make_float4(acc[k][4 * jq + 0] * scale, acc[k][4 * jq + 1] * scale,
                                  acc[k][4 * jq + 2] * scale, acc[k][4 * jq + 3] * scale);
        }
    }
}

// mode 0: g_Ocum = squash(s); mode 1: g_Ocum += squash(s); mode 2: out = squash(s)
__global__ void caps_reduce(float* __restrict__ out, int mode) {
    const int idx = blockIdx.x * 256 + threadIdx.x;   // 0..32767 = (b*32+c)*16+j
    float s0 = 0.f, s1 = 0.f, s2 = 0.f, s3 = 0.f;
    #pragma unroll 4
    for (int k = 0; k < NCTA; k += 4) {
        s0 += g_part[(size_t)k       * (B_ * C_ * D_) + idx];
        s1 += g_part[(size_t)(k + 1) * (B_ * C_ * D_) + idx];
        s2 += g_part[(size_t)(k + 2) * (B_ * C_ * D_) + idx];
        s3 += g_part[(size_t)(k + 3) * (B_ * C_ * D_) + idx];
    }
    const float s = (s0 + s1) + (s2 + s3);
    float sq = s * s;   // reduce over j (16 consecutive lanes)
    sq += __shfl_xor_sync(0xffffffffu, sq, 1);
    sq += __shfl_xor_sync(0xffffffffu, sq, 2);
    sq += __shfl_xor_sync(0xffffffffu, sq, 4);
    sq += __shfl_xor_sync(0xffffffffu, sq, 8);
    const float v = s * (sq / ((1.f + sq) * sqrtf(sq + 1e-7f)));
    if (mode == 0)      g_Ocum[idx] = v;
    else if (mode == 1) g_Ocum[idx] += v;
    else                out[idx] = v;
}

extern "C" void kernel_launch(void* const* d_in, const int* in_sizes, int n_in,
                              void* d_out, int out_size) {
    const float* X = (const float*)d_in[0];
    const float* W = (const float*)d_in[1];
    // defensive: pick by element count (inputs: 2,097,152 ; W: 16,777,216)
    if (n_in >= 2 && in_sizes[0] != B_ * N_ * I_) {
        X = (const float*)d_in[1];
        W = (const float*)d_in[0];
    }
    float* out = (float*)d_out;

    const int smem0  = (SUBN * C_ * D_ * I_ + NCHUNK * NB * I_) * 4;          // 98304 B
    const int smem12 = smem0 + NB * C_ * OPAD * 4;                             // 180224 B
    cudaFuncSetAttribute(caps_pass<0>, cudaFuncAttributeMaxDynamicSharedMemorySize, smem0);
    cudaFuncSetAttribute(caps_pass<1>, cudaFuncAttributeMaxDynamicSharedMemorySize, smem12);
    cudaFuncSetAttribute(caps_pass<2>, cudaFuncAttributeMaxDynamicSharedMemorySize, smem12);

    dim3 grid(NCTA, 2);
    caps_pass<0><<<grid, THREADS, smem0 >>>(X, W);
    caps_reduce <<<128, 256>>>(out, 0);
    caps_pass<1><<<grid, THREADS, smem12>>>(X, W);
    caps_reduce <<<128, 256>>>(out, 1);
    caps_pass<2><<<grid, THREADS, smem12>>>(X, W);
    caps_reduce <<<128, 256>>>(out, 2);
}

// round 3
// speedup vs baseline: 1.9093x; 1.9093x over previous
#include <cuda_runtime.h>

// Capsule dynamic routing, fused recompute. B=64, N=4096, I=8, C=32, D=16, 3 iters.
// Pass kernel: grid (64 chunks, 2 b-halves), 256 thr. lane=c, warp w -> local b 4w..4w+3.
// W staged j-pair-interleaved + xor-swizzled in smem; hat/logit/acc all fma.rn.f32x2.
// Iter0 fuses hat directly into accumulators (uniform coupling). Partials -> g_part,
// reduce kernel sums 64 chunks + squash + maintains cumulative-out for logits.

#define B_ 64
#define N_ 4096
#define C_ 32
#define NCHUNK 64
#define SUBN 4
#define NCH 64          // N_/NCHUNK
#define THREADS 256

using u64 = unsigned long long;

__device__ float g_part[(size_t)NCH * B_ * C_ * 16];   // 8MB  [chunk][b][c][j]
__device__ float g_Ocum[B_ * C_ * 16];                  // cumulative sum of outs

__device__ __forceinline__ u64 fma2(u64 a, u64 b, u64 c) {
    u64 d; asm("fma.rn.f32x2 %0,%1,%2,%3;" : "=l"(d) : "l"(a), "l"(b), "l"(c)); return d;
}
__device__ __forceinline__ u64 mul2(u64 a, u64 b) {
    u64 d; asm("mul.rn.f32x2 %0,%1,%2;" : "=l"(d) : "l"(a), "l"(b)); return d;
}
__device__ __forceinline__ u64 pack2(float x) {
    u64 d; asm("mov.b64 %0,{%1,%1};" : "=l"(d) : "f"(x)); return d;
}
__device__ __forceinline__ float hadd2(u64 v) {
    float a, b; asm("mov.b64 {%0,%1},%2;" : "=f"(a), "=f"(b) : "l"(v)); return a + b;
}
__device__ __forceinline__ float2 unpk(u64 v) {
    float a, b; asm("mov.b64 {%0,%1},%2;" : "=f"(a), "=f"(b) : "l"(v)); return make_float2(a, b);
}

// smem: sW 16384 fl (SUBN n, unit f4 = (w[2jp][2iq],w[2jp+1][2iq],w[2jp][2iq+1],w[2jp+1][2iq+1]),
//        row r=nn*32+jp*4+iq, f4 slot = r*32 + (c ^ (r&31)) )
//       sX 16384 fl ([bl][nn*2+ih] f4)    sO 16384 fl ([bl][q][c] f4, ITER>0)
template<int ITER>
__global__ void __launch_bounds__(THREADS, 1)
caps_pass(const float* __restrict__ X, const float* __restrict__ W) {
    extern __shared__ float sm[];
    float* sW = sm;                         // 64KB
    float* sX = sm + SUBN * 4096;           // 64KB
    float* sO = sX + NCHUNK * 32 * 8;       // 64KB (ITER>0 only)

    const int chunk = blockIdx.x, half = blockIdx.y;
    const int n0 = chunk * NCHUNK, b0 = half * 32;
    const int tid = threadIdx.x;
    const int c = tid & 31, w = tid >> 5;

    // ---- stage X: sX[bl][r], r = nn*2+ih ----
    for (int t = tid; t < NCHUNK * 32 * 2; t += THREADS) {
        int bl = t >> 7, r = t & 127;
        float4 v = reinterpret_cast<const float4*>(X)[(size_t)(b0 + bl) * (N_ * 2) + (size_t)n0 * 2 + r];
        reinterpret_cast<float4*>(sX)[bl * 128 + r] = v;
    }
    // ---- stage O: sO[bl][q][c] (pairs (o2q,o2q+1) natural in f4) ----
    if (ITER > 0) {
        for (int t = tid; t < 32 * 4 * C_; t += THREADS) {
            int cc = t & 31, q = (t >> 5) & 3, bl = t >> 7;
            float4 v = reinterpret_cast<const float4*>(g_Ocum)[((b0 + bl) * C_ + cc) * 4 + q];
            reinterpret_cast<float4*>(sO)[bl * 128 + q * 32 + cc] = v;
        }
    }

    u64 acc[4][8];
    #pragma unroll
    for (int bi = 0; bi < 4; ++bi)
        #pragma unroll
        for (int jp = 0; jp < 8; ++jp) acc[bi][jp] = 0ull;

    for (int sub = 0; sub < NCHUNK / SUBN; ++sub) {
        __syncthreads();
        // ---- stage W sub-chunk, pair-interleaved + swizzled ----
        {
            const int nb = n0 + sub * SUBN;
            for (int t = tid; t < 512 * SUBN; t += THREADS) {
                int ih = t & 1, jp = (t >> 1) & 7, nn = (t >> 4) & 3, cc = t >> 6;
                const float4* gp = reinterpret_cast<const float4*>(W)
                                     + ((size_t)cc * N_ + (nb + nn)) * 32 + jp * 4 + ih;
                float4 A = gp[0], Bv = gp[2];
                int r0 = nn * 32 + jp * 4 + 2 * ih;
                reinterpret_cast<float4*>(sW)[(r0 << 5) + (cc ^ (r0 & 31))] =
                    make_float4(A.x, Bv.x, A.y, Bv.y);
                int r1 = r0 + 1;
                reinterpret_cast<float4*>(sW)[(r1 << 5) + (cc ^ (r1 & 31))] =
                    make_float4(A.z, Bv.z, A.w, Bv.w);
            }
        }
        __syncthreads();

        #pragma unroll 1
        for (int nn = 0; nn < SUBN; ++nn) {
            u64 hat[4][8];
            #pragma unroll
            for (int h = 0; h < 2; ++h) {
                // load W half: 16 f4 -> 32 u64 (pair operands)
                u64 Wlo[16], Whi[16];
                #pragma unroll
                for (int k = 0; k < 16; ++k) {
                    int r = nn * 32 + h * 16 + k;
                    ulonglong2 u = reinterpret_cast<const ulonglong2*>(sW)[(r << 5) + (c ^ (r & 31))];
                    Wlo[k] = u.x; Whi[k] = u.y;
                }
                #pragma unroll
                for (int bi = 0; bi < 4; ++bi) {
                    const int bl = w * 4 + bi;
                    const float4* xp = reinterpret_cast<const float4*>(sX)
                                         + bl * 128 + (sub * SUBN + nn) * 2;
                    float4 x0 = xp[0], x1 = xp[1];
                    u64 xa = pack2(x0.x), xb = pack2(x0.y), xc = pack2(x0.z), xd = pack2(x0.w);
                    u64 xe = pack2(x1.x), xf = pack2(x1.y), xg = pack2(x1.z), xh = pack2(x1.w);
                    #pragma unroll
                    for (int jl = 0; jl < 4; ++jl) {
                        const int k4 = jl * 4;
                        if (ITER == 0) {
                            u64 t = acc[bi][h * 4 + jl];   // fuse into accumulator
                            t = fma2(xa, Wlo[k4 + 0], t); t = fma2(xb, Whi[k4 + 0], t);
                            t = fma2(xc, Wlo[k4 + 1], t); t = fma2(xd, Whi[k4 + 1], t);
                            t = fma2(xe, Wlo[k4 + 2], t); t = fma2(xf, Whi[k4 + 2], t);
                            t = fma2(xg, Wlo[k4 + 3], t); t = fma2(xh, Whi[k4 + 3], t);
                            acc[bi][h * 4 + jl] = t;
                        } else {
                            u64 t = mul2(xa, Wlo[k4 + 0]);
                            t = fma2(xb, Whi[k4 + 0], t);
                            t = fma2(xc, Wlo[k4 + 1], t); t = fma2(xd, Whi[k4 + 1], t);
                            t = fma2(xe, Wlo[k4 + 2], t); t = fma2(xf, Whi[k4 + 2], t);
                            t = fma2(xg, Wlo[k4 + 3], t); t = fma2(xh, Whi[k4 + 3], t);
                            hat[bi][h * 4 + jl] = t;
                        }
                    }
                }
            }
            if (ITER > 0) {
                #pragma unroll
                for (int bi = 0; bi < 4; ++bi) {
                    const int bl = w * 4 + bi;
                    const ulonglong2* op = reinterpret_cast<const ulonglong2*>(sO) + bl * 128 + c;
                    ulonglong2 o0 = op[0], o1 = op[32], o2 = op[64], o3 = op[96];
                    u64 lg = mul2(hat[bi][0], o0.x);
                    lg = fma2(hat[bi][1], o0.y, lg);
                    lg = fma2(hat[bi][2], o1.x, lg); lg = fma2(hat[bi][3], o1.y, lg);
                    lg = fma2(hat[bi][4], o2.x, lg); lg = fma2(hat[bi][5], o2.y, lg);
                    lg = fma2(hat[bi][6], o3.x, lg); lg = fma2(hat[bi][7], o3.y, lg);
                    const float logit = hadd2(lg);
                    const float e = __expf(logit);    // logits O(1): no max-sub needed
                    float s = e;
                    s += __shfl_xor_sync(0xffffffffu, s, 1);
                    s += __shfl_xor_sync(0xffffffffu, s, 2);
                    s += __shfl_xor_sync(0xffffffffu, s, 4);
                    s += __shfl_xor_sync(0xffffffffu, s, 8);
                    s += __shfl_xor_sync(0xffffffffu, s, 16);
                    const u64 cf2 = pack2(__fdividef(e, s));
                    #pragma unroll
                    for (int jp = 0; jp < 8; ++jp)
                        acc[bi][jp] = fma2(cf2, hat[bi][jp], acc[bi][jp]);
                }
            }
        }
    }

    // ---- flush partials ----
    const float scale = (ITER == 0) ? (1.f / 32.f) : 1.f;
    #pragma unroll
    for (int bi = 0; bi < 4; ++bi) {
        const int b = b0 + w * 4 + bi;
        float4* dst = reinterpret_cast<float4*>(g_part)
                        + (((size_t)chunk * B_ + b) * C_ + c) * 4;
        #pragma unroll
        for (int q = 0; q < 4; ++q) {
            float2 p0 = unpk(acc[bi][2 * q]), p1 = unpk(acc[bi][2 * q + 1]);
            dst[q] = make_float4(p0.x * scale, p0.y * scale, p1.x * scale, p1.y * scale);
        }
    }
}

// mode 0: g_Ocum = squash(s); 1: g_Ocum += squash(s); 2: out = squash(s)
__global__ void caps_reduce(float* __restrict__ out, int mode) {
    const int idx4 = blockIdx.x * 256 + threadIdx.x;   // 0..8191 = ((b*32+c)*4+q)
    float4 a0 = make_float4(0.f, 0.f, 0.f, 0.f), a1 = a0, a2 = a0, a3 = a0;
    #pragma unroll 4
    for (int k = 0; k < NCH; k += 4) {
        float4 v0 = reinterpret_cast<const float4*>(g_part)[(size_t)(k + 0) * 8192 + idx4];
        float4 v1 = reinterpret_cast<const float4*>(g_part)[(size_t)(k + 1) * 8192 + idx4];
        float4 v2 = reinterpret_cast<const float4*>(g_part)[(size_t)(k + 2) * 8192 + idx4];
        float4 v3 = reinterpret_cast<const float4*>(g_part)[(size_t)(k + 3) * 8192 + idx4];
        a0.x += v0.x; a0.y += v0.y; a0.z += v0.z; a0.w += v0.w;
        a1.x += v1.x; a1.y += v1.y; a1.z += v1.z; a1.w += v1.w;
        a2.x += v2.x; a2.y += v2.y; a2.z += v2.z; a2.w += v2.w;
        a3.x += v3.x; a3.y += v3.y; a3.z += v3.z; a3.w += v3.w;
    }
    float4 s = make_float4((a0.x + a1.x) + (a2.x + a3.x), (a0.y + a1.y) + (a2.y + a3.y),
                           (a0.z + a1.z) + (a2.z + a3.z), (a0.w + a1.w) + (a2.w + a3.w));
    float sq = s.x * s.x + s.y * s.y + s.z * s.z + s.w * s.w;
    sq += __shfl_xor_sync(0xffffffffu, sq, 1);
    sq += __shfl_xor_sync(0xffffffffu, sq, 2);
    const float f = sq / ((1.f + sq) * sqrtf(sq + 1e-7f));
    float4 v = make_float4(s.x * f, s.y * f, s.z * f, s.w * f);
    float4* oc = reinterpret_cast<float4*>(g_Ocum);
    if (mode == 0) {
        oc[idx4] = v;
    } else if (mode == 1) {
        float4 o = oc[idx4];
        o.x += v.x; o.y += v.y; o.z += v.z; o.w += v.w;
        oc[idx4] = o;
    } else {
        reinterpret_cast<float4*>(out)[idx4] = v;
    }
}

extern "C" void kernel_launch(void* const* d_in, const int* in_sizes, int n_in,
                              void* d_out, int out_size) {
    const float* X = (const float*)d_in[0];
    const float* W = (const float*)d_in[1];
    if (n_in >= 2 && in_sizes[0] != B_ * N_ * 8) {   // defensive input-order check
        X = (const float*)d_in[1];
        W = (const float*)d_in[0];
    }
    float* out = (float*)d_out;

    const int smem0  = (SUBN * 4096 + NCHUNK * 32 * 8) * 4;          // 131072 B
    const int smem12 = smem0 + 32 * C_ * 16 * 4;                     // 196608 B
    cudaFuncSetAttribute(caps_pass<0>, cudaFuncAttributeMaxDynamicSharedMemorySize, smem0);
    cudaFuncSetAttribute(caps_pass<1>, cudaFuncAttributeMaxDynamicSharedMemorySize, smem12);
    cudaFuncSetAttribute(caps_pass<2>, cudaFuncAttributeMaxDynamicSharedMemorySize, smem12);

    dim3 grid(NCH, 2);
    caps_pass<0><<<grid, THREADS, smem0 >>>(X, W);
    caps_reduce <<<32, 256>>>(out, 0);
    caps_pass<1><<<grid, THREADS, smem12>>>(X, W);
    caps_reduce <<<32, 256>>>(out, 1);
    caps_pass<2><<<grid, THREADS, smem12>>>(X, W);
    caps_reduce <<<32, 256>>>(out, 2);
}

// round 4
// speedup vs baseline: 2.4107x; 1.2626x over previous
#include <cuda_runtime.h>

// Capsule dynamic routing. B=64, N=4096, I=8, C=32, D=16, 3 routing iters.
// prep_W: one-time interleave of W into g_Wil[n][r][c] (r=jp*4+i2; f4 = j-pair
//   values for i=2i2,2i2+1) enabling linear cp.async staging.
// caps_pass0: uniform coupling; 8 b/thread, all 64 b per CTA, 32 n/CTA, grid 128.
// caps_pass12: 4 b/thread, 32 b + 64 n per CTA, grid (64,2); o hoisted to regs;
//   hat/logit/acc in fma.rn.f32x2; softmax = full-warp shfl (lane = c).
// caps_reduce: 128 CTAs, chunks split 4-way across lanes, shfl merge + squash.

#define B_ 64
#define N_ 4096
#define C_ 32

using u64 = unsigned long long;

__device__ float4 g_Wil[(size_t)N_ * 1024];              // 64MB interleaved W
__device__ float g_part[(size_t)128 * B_ * C_ * 16];     // 16MB partials
__device__ float g_Ocum[B_ * C_ * 16];                   // cumulative outs

__device__ __forceinline__ u64 fma2(u64 a, u64 b, u64 c) {
    u64 d; asm("fma.rn.f32x2 %0,%1,%2,%3;" : "=l"(d) : "l"(a), "l"(b), "l"(c)); return d;
}
__device__ __forceinline__ u64 mul2(u64 a, u64 b) {
    u64 d; asm("mul.rn.f32x2 %0,%1,%2;" : "=l"(d) : "l"(a), "l"(b)); return d;
}
__device__ __forceinline__ u64 pack2(float x) {
    u64 d; asm("mov.b64 %0,{%1,%1};" : "=l"(d) : "f"(x)); return d;
}
__device__ __forceinline__ float hadd2(u64 v) {
    float a, b; asm("mov.b64 {%0,%1},%2;" : "=f"(a), "=f"(b) : "l"(v)); return a + b;
}
__device__ __forceinline__ float2 unpk(u64 v) {
    float a, b; asm("mov.b64 {%0,%1},%2;" : "=f"(a), "=f"(b) : "l"(v)); return make_float2(a, b);
}
__device__ __forceinline__ unsigned smem_u32(const void* p) {
    unsigned a; asm("{ .reg .u64 t; cvta.to.shared.u64 t, %1; cvt.u32.u64 %0, t; }" : "=r"(a) : "l"(p));
    return a;
}
__device__ __forceinline__ void cpa16(unsigned dst, const void* src) {
    asm volatile("cp.async.cg.shared.global [%0], [%1], 16;" :: "r"(dst), "l"(src));
}
__device__ __forceinline__ void cpa_commit() { asm volatile("cp.async.commit_group;"); }
__device__ __forceinline__ void cpa_wait1() { asm volatile("cp.async.wait_group 1;"); }
__device__ __forceinline__ void cpa_wait0() { asm volatile("cp.async.wait_group 0;"); }

// ---------------- W interleave prepass: grid 4096 x 256 ----------------
__global__ void prep_W(const float* __restrict__ W) {
    const int tid = threadIdx.x;
    const int c = tid & 31, jp = tid >> 5;          // jp 0..7
    const int n = blockIdx.x;
    const float4* gp = reinterpret_cast<const float4*>(W)
                         + (((size_t)c * N_ + n) * 16 + 2 * jp) * 2;
    float4 A0 = gp[0], A1 = gp[1], B0 = gp[2], B1 = gp[3];  // rows j=2jp, 2jp+1
    float4* dst = g_Wil + (size_t)n * 1024 + (jp * 4) * 32 + c;
    dst[0]  = make_float4(A0.x, B0.x, A0.y, B0.y);   // i2=0
    dst[32] = make_float4(A0.z, B0.z, A0.w, B0.w);   // i2=1
    dst[64] = make_float4(A1.x, B1.x, A1.y, B1.y);   // i2=2
    dst[96] = make_float4(A1.z, B1.z, A1.w, B1.w);   // i2=3
}

// ---------------- pass 0: uniform coupling, 8 b/thread ----------------
// grid 128 (chunks of 32 n), 256 thr. smem: sW 64KB (2 buf x 2n x 16KB) + sXp 128KB.
__global__ void __launch_bounds__(256, 1)
caps_pass0(const float* __restrict__ X) {
    extern __shared__ char smraw[];
    float4* sW = reinterpret_cast<float4*>(smraw);               // 4096 f4
    u64* sXp = reinterpret_cast<u64*>(smraw + 65536);            // [bl][n][i] dup pairs
    const int chunk = blockIdx.x, n0 = chunk * 32;
    const int tid = threadIdx.x, c = tid & 31, w = tid >> 5;
    const unsigned sWa = smem_u32(sW);

    // stage X as duplicated pairs
    for (int t = tid; t < 64 * 32 * 2; t += 256) {
        int bl = t >> 6, rem = t & 63;                           // rem = n*2+ih
        float4 v = reinterpret_cast<const float4*>(X)[(size_t)bl * 8192 + n0 * 2 + rem];
        ulonglong2* d = reinterpret_cast<ulonglong2*>(sXp + bl * 256 + (rem >> 1) * 8 + (rem & 1) * 4);
        d[0] = make_ulonglong2(pack2(v.x), pack2(v.y));
        d[1] = make_ulonglong2(pack2(v.z), pack2(v.w));
    }

    u64 acc[8][8];
    #pragma unroll
    for (int bi = 0; bi < 8; ++bi)
        #pragma unroll
        for (int jp = 0; jp < 8; ++jp) acc[bi][jp] = 0ull;

    // double-buffered W staging: 2 n (2048 f4 = 32KB) per sub
    auto stage = [&](int sub, int buf) {
        const float4* src = g_Wil + (size_t)(n0 + sub * 2) * 1024;
        unsigned dst = sWa + (unsigned)(buf * 2048 + tid) * 16;
        #pragma unroll
        for (int k = 0; k < 8; ++k) cpa16(dst + k * 4096, src + tid + k * 256);
        cpa_commit();
    };
    stage(0, 0);

    for (int sub = 0; sub < 16; ++sub) {
        if (sub < 15) { stage(sub + 1, (sub + 1) & 1); cpa_wait1(); }
        else cpa_wait0();
        __syncthreads();
        const float4* Wb = sW + (sub & 1) * 2048;
        #pragma unroll
        for (int ln = 0; ln < 2; ++ln) {
            const float4* Wn = Wb + ln * 1024;
            const int nloc = sub * 2 + ln;
            #pragma unroll
            for (int q = 0; q < 4; ++q) {
                ulonglong2 Wq[8];
                #pragma unroll
                for (int k = 0; k < 8; ++k)
                    Wq[k] = reinterpret_cast<const ulonglong2*>(Wn + (q * 8 + k) * 32)[c];
                #pragma unroll
                for (int bi = 0; bi < 8; ++bi) {
                    const ulonglong2* xp = reinterpret_cast<const ulonglong2*>(
                        sXp + (w * 8 + bi) * 256 + nloc * 8);
                    ulonglong2 xA = xp[0], xB = xp[1], xC = xp[2], xD = xp[3];
                    u64 a0 = acc[bi][2 * q], a1 = acc[bi][2 * q + 1];
                    a0 = fma2(xA.x, Wq[0].x, a0); a0 = fma2(xA.y, Wq[0].y, a0);
                    a0 = fma2(xB.x, Wq[1].x, a0); a0 = fma2(xB.y, Wq[1].y, a0);
                    a0 = fma2(xC.x, Wq[2].x, a0); a0 = fma2(xC.y, Wq[2].y, a0);
                    a0 = fma2(xD.x, Wq[3].x, a0); a0 = fma2(xD.y, Wq[3].y, a0);
                    a1 = fma2(xA.x, Wq[4].x, a1); a1 = fma2(xA.y, Wq[4].y, a1);
                    a1 = fma2(xB.x, Wq[5].x, a1); a1 = fma2(xB.y, Wq[5].y, a1);
                    a1 = fma2(xC.x, Wq[6].x, a1); a1 = fma2(xC.y, Wq[6].y, a1);
                    a1 = fma2(xD.x, Wq[7].x, a1); a1 = fma2(xD.y, Wq[7].y, a1);
                    acc[bi][2 * q] = a0; acc[bi][2 * q + 1] = a1;
                }
            }
        }
        __syncthreads();
    }

    #pragma unroll
    for (int bi = 0; bi < 8; ++bi) {
        const int b = w * 8 + bi;
        float4* dst = reinterpret_cast<float4*>(g_part) + (((size_t)chunk * B_ + b) * C_ + c) * 4;
        #pragma unroll
        for (int qd = 0; qd < 4; ++qd) {
            float2 p0 = unpk(acc[bi][2 * qd]), p1 = unpk(acc[bi][2 * qd + 1]);
            dst[qd] = make_float4(p0.x * (1.f / 32.f), p0.y * (1.f / 32.f),
                                  p1.x * (1.f / 32.f), p1.y * (1.f / 32.f));
        }
    }
}

// ---------------- pass 1/2: routed coupling, 4 b/thread, o in regs ----------------
// grid (64 chunks, 2 b-halves), 256 thr. smem: sW 64KB + sXp 128KB.
__global__ void __launch_bounds__(256, 1)
caps_pass12(const float* __restrict__ X) {
    extern __shared__ char smraw[];
    float4* sW = reinterpret_cast<float4*>(smraw);
    u64* sXp = reinterpret_cast<u64*>(smraw + 65536);            // [bl 32][n 64][i 8]
    const int chunk = blockIdx.x, half = blockIdx.y;
    const int n0 = chunk * 64, b0 = half * 32;
    const int tid = threadIdx.x, c = tid & 31, w = tid >> 5;
    const unsigned sWa = smem_u32(sW);

    for (int t = tid; t < 32 * 64 * 2; t += 256) {
        int bl = t >> 7, rem = t & 127;
        float4 v = reinterpret_cast<const float4*>(X)[(size_t)(b0 + bl) * 8192 + n0 * 2 + rem];
        ulonglong2* d = reinterpret_cast<ulonglong2*>(sXp + bl * 512 + (rem >> 1) * 8 + (rem & 1) * 4);
        d[0] = make_ulonglong2(pack2(v.x), pack2(v.y));
        d[1] = make_ulonglong2(pack2(v.z), pack2(v.w));
    }

    // hoist o (cumulative outs) to registers: loop-invariant over n
    u64 o2[4][8];
    #pragma unroll
    for (int bi = 0; bi < 4; ++bi) {
        const int b = b0 + w * 4 + bi;
        const ulonglong2* op = reinterpret_cast<const ulonglong2*>(g_Ocum + (b * C_ + c) * 16);
        #pragma unroll
        for (int qd = 0; qd < 4; ++qd) {
            ulonglong2 u = op[qd];
            o2[bi][2 * qd] = u.x; o2[bi][2 * qd + 1] = u.y;
        }
    }

    u64 acc[4][8];
    #pragma unroll
    for (int bi = 0; bi < 4; ++bi)
        #pragma unroll
        for (int jp = 0; jp < 8; ++jp) acc[bi][jp] = 0ull;

    auto stage = [&](int sub, int buf) {
        const float4* src = g_Wil + (size_t)(n0 + sub * 2) * 1024;
        unsigned dst = sWa + (unsigned)(buf * 2048 + tid) * 16;
        #pragma unroll
        for (int k = 0; k < 8; ++k) cpa16(dst + k * 4096, src + tid + k * 256);
        cpa_commit();
    };
    stage(0, 0);

    for (int sub = 0; sub < 32; ++sub) {
        if (sub < 31) { stage(sub + 1, (sub + 1) & 1); cpa_wait1(); }
        else cpa_wait0();
        __syncthreads();
        const float4* Wb = sW + (sub & 1) * 2048;
        #pragma unroll
        for (int ln = 0; ln < 2; ++ln) {
            const float4* Wn = Wb + ln * 1024;
            const int nloc = sub * 2 + ln;
            u64 hat[4][8];
            #pragma unroll
            for (int q = 0; q < 4; ++q) {
                ulonglong2 Wq[8];
                #pragma unroll
                for (int k = 0; k < 8; ++k)
                    Wq[k] = reinterpret_cast<const ulonglong2*>(Wn + (q * 8 + k) * 32)[c];
                #pragma unroll
                for (int bi = 0; bi < 4; ++bi) {
                    const ulonglong2* xp = reinterpret_cast<const ulonglong2*>(
                        sXp + (w * 4 + bi) * 512 + nloc * 8);
                    ulonglong2 xA = xp[0], xB = xp[1], xC = xp[2], xD = xp[3];
                    u64 h0 = mul2(xA.x, Wq[0].x);
                    h0 = fma2(xA.y, Wq[0].y, h0);
                    h0 = fma2(xB.x, Wq[1].x, h0); h0 = fma2(xB.y, Wq[1].y, h0);
                    h0 = fma2(xC.x, Wq[2].x, h0); h0 = fma2(xC.y, Wq[2].y, h0);
                    h0 = fma2(xD.x, Wq[3].x, h0); h0 = fma2(xD.y, Wq[3].y, h0);
                    u64 h1 = mul2(xA.x, Wq[4].x);
                    h1 = fma2(xA.y, Wq[4].y, h1);
                    h1 = fma2(xB.x, Wq[5].x, h1); h1 = fma2(xB.y, Wq[5].y, h1);
                    h1 = fma2(xC.x, Wq[6].x, h1); h1 = fma2(xC.y, Wq[6].y, h1);
                    h1 = fma2(xD.x, Wq[7].x, h1); h1 = fma2(xD.y, Wq[7].y, h1);
                    hat[bi][2 * q] = h0; hat[bi][2 * q + 1] = h1;
                }
            }
            #pragma unroll
            for (int bi = 0; bi < 4; ++bi) {
                u64 lg = mul2(hat[bi][0], o2[bi][0]);
                lg = fma2(hat[bi][1], o2[bi][1], lg);
                lg = fma2(hat[bi][2], o2[bi][2], lg); lg = fma2(hat[bi][3], o2[bi][3], lg);
                lg = fma2(hat[bi][4], o2[bi][4], lg); lg = fma2(hat[bi][5], o2[bi][5], lg);
                lg = fma2(hat[bi][6], o2[bi][6], lg); lg = fma2(hat[bi][7], o2[bi][7], lg);
                const float e = __expf(hadd2(lg));   // logits O(1): no max-sub needed
                float s = e;
                s += __shfl_xor_sync(0xffffffffu, s, 1);
                s += __shfl_xor_sync(0xffffffffu, s, 2);
                s += __shfl_xor_sync(0xffffffffu, s, 4);
                s += __shfl_xor_sync(0xffffffffu, s, 8);
                s += __shfl_xor_sync(0xffffffffu, s, 16);
                const u64 cf = pack2(__fdividef(e, s));
                #pragma unroll
                for (int jp = 0; jp < 8; ++jp)
                    acc[bi][jp] = fma2(cf, hat[bi][jp], acc[bi][jp]);
            }
        }
        __syncthreads();
    }

    #pragma unroll
    for (int bi = 0; bi < 4; ++bi) {
        const int b = b0 + w * 4 + bi;
        float4* dst = reinterpret_cast<float4*>(g_part) + (((size_t)chunk * B_ + b) * C_ + c) * 4;
        #pragma unroll
        for (int qd = 0; qd < 4; ++qd) {
            float2 p0 = unpk(acc[bi][2 * qd]), p1 = unpk(acc[bi][2 * qd + 1]);
            dst[qd] = make_float4(p0.x, p0.y, p1.x, p1.y);
        }
    }
}

// ---------------- reduce + squash: grid 128 x 256 ----------------
// thread: idx4 = gt>>2 (f4 output), quarter = gt&3 handles nch/4 chunks.
__global__ void caps_reduce(float* __restrict__ out, int mode, int nch) {
    const int gt = blockIdx.x * 256 + threadIdx.x;
    const int idx4 = gt >> 2, quarter = gt & 3;
    const int kc = nch >> 2;
    float4 a = make_float4(0.f, 0.f, 0.f, 0.f);
    const float4* gp = reinterpret_cast<const float4*>(g_part) + idx4;
    #pragma unroll 8
    for (int k = 0; k < kc; ++k) {
        float4 v = gp[(size_t)(quarter * kc + k) * 8192];
        a.x += v.x; a.y += v.y; a.z += v.z; a.w += v.w;
    }
    // merge quarters (lanes xor 1,2 share idx4)
    a.x += __shfl_xor_sync(0xffffffffu, a.x, 1); a.y += __shfl_xor_sync(0xffffffffu, a.y, 1);
    a.z += __shfl_xor_sync(0xffffffffu, a.z, 1); a.w += __shfl_xor_sync(0xffffffffu, a.w, 1);
    a.x += __shfl_xor_sync(0xffffffffu, a.x, 2); a.y += __shfl_xor_sync(0xffffffffu, a.y, 2);
    a.z += __shfl_xor_sync(0xffffffffu, a.z, 2); a.w += __shfl_xor_sync(0xffffffffu, a.w, 2);
    // squash: ||s||^2 over 16 j = 4 idx4 (lanes xor 4,8)
    float sq = a.x * a.x + a.y * a.y + a.z * a.z + a.w * a.w;
    sq += __shfl_xor_sync(0xffffffffu, sq, 4);
    sq += __shfl_xor_sync(0xffffffffu, sq, 8);
    const float f = sq / ((1.f + sq) * sqrtf(sq + 1e-7f));
    float4 v = make_float4(a.x * f, a.y * f, a.z * f, a.w * f);
    if (quarter == 0) {
        float4* oc = reinterpret_cast<float4*>(g_Ocum);
        if (mode == 0) {
            oc[idx4] = v;
        } else if (mode == 1) {
            float4 o = oc[idx4];
            o.x += v.x; o.y += v.y; o.z += v.z; o.w += v.w;
            oc[idx4] = o;
        } else {
            reinterpret_cast<float4*>(out)[idx4] = v;
        }
    }
}

extern "C" void kernel_launch(void* const* d_in, const int* in_sizes, int n_in,
                              void* d_out, int out_size) {
    const float* X = (const float*)d_in[0];
    const float* W = (const float*)d_in[1];
    if (n_in >= 2 && in_sizes[0] != B_ * N_ * 8) {
        X = (const float*)d_in[1];
        W = (const float*)d_in[0];
    }
    float* out = (float*)d_out;

    const int smem = 65536 + 131072;   // sW 64KB + sXp 128KB = 192KB
    cudaFuncSetAttribute(caps_pass0,  cudaFuncAttributeMaxDynamicSharedMemorySize, smem);
    cudaFuncSetAttribute(caps_pass12, cudaFuncAttributeMaxDynamicSharedMemorySize, smem);

    prep_W<<<N_, 256>>>(W);
    caps_pass0<<<128, 256, smem>>>(X);
    caps_reduce<<<128, 256>>>(out, 0, 128);
    caps_pass12<<<dim3(64, 2), 256, smem>>>(X);
    caps_reduce<<<128, 256>>>(out, 1, 64);
    caps_pass12<<<dim3(64, 2), 256, smem>>>(X);
    caps_reduce<<<128, 256>>>(out, 2, 64);
}